// round 5
// baseline (speedup 1.0000x reference)
#include <cuda_runtime.h>

typedef unsigned long long ull;

#define CDIM 512
#define MDIM 320
#define LCLS 10
#define SHRINK_L 0.0025f
#define EPS_F 1e-12f

#define BM 64
#define THREADS 256

// shared memory layout (float offsets)
#define OFF_ATT 0            // 64*320  = 20480 floats
#define OFF_SEM 20480        // 10*512  = 5120
#define OFF_WS  25600        // 32*322  = 10304 (also reused as 32*260)
#define OFF_XS  35904        // 64*36   = 2304
#define SMEM_FLOATS 38208
#define WS_STRIDE  322
#define WS2_STRIDE 260
#define XS_STRIDE  36

__device__ float g_sem[LCLS * CDIM];

__device__ __forceinline__ float sigmoidf_(float x) { return 1.0f / (1.0f + __expf(-x)); }

__device__ __forceinline__ ull pack2(float lo, float hi) {
    ull r; asm("mov.b64 %0, {%1, %2};" : "=l"(r) : "f"(lo), "f"(hi)); return r;
}
__device__ __forceinline__ void unpack2(ull v, float& lo, float& hi) {
    asm("mov.b64 {%0, %1}, %2;" : "=f"(lo), "=f"(hi) : "l"(v));
}
__device__ __forceinline__ void ffma2(ull& d, ull a, ull b) {
    asm("fma.rn.f32x2 %0, %1, %2, %0;" : "+l"(d) : "l"(a), "l"(b));
}

__device__ __forceinline__ float wr_max(float v) {
    #pragma unroll
    for (int o = 16; o; o >>= 1) v = fmaxf(v, __shfl_xor_sync(0xffffffffu, v, o));
    return v;
}
__device__ __forceinline__ float wr_sum(float v) {
    #pragma unroll
    for (int o = 16; o; o >>= 1) v += __shfl_xor_sync(0xffffffffu, v, o);
    return v;
}

// ---------------------------------------------------------------------------
// Kernel A: build sem_att [10, 512] from W, wp, bp, wi, bi. One block, 512 thr.
// rp[n,p,c] = W_flat[n*2048 + c*4 + p]
// part[n,c] = mean_q sigmoid(sum_p wp[q,p]*rp[n,p,c] + bp[q]) * rp[n,q,c]
// sem[l,c]  = mean_q sigmoid(sum_t wi[q,t]*part[l*8+t,c] + bi[q]) * part[l*8+q,c]
// ---------------------------------------------------------------------------
__global__ void sem_build_kernel(const float* __restrict__ W,
                                 const float* __restrict__ wp,
                                 const float* __restrict__ bp,
                                 const float* __restrict__ wi,
                                 const float* __restrict__ bi,
                                 float* __restrict__ out_semmat) {
    int c = threadIdx.x;
    if (c >= CDIM) return;

    float wpl[16], bpl[4], wil[64], bil[8];
    #pragma unroll
    for (int i = 0; i < 16; ++i) wpl[i] = wp[i];
    #pragma unroll
    for (int i = 0; i < 4; ++i) bpl[i] = bp[i];
    #pragma unroll
    for (int i = 0; i < 64; ++i) wil[i] = wi[i];
    #pragma unroll
    for (int i = 0; i < 8; ++i) bil[i] = bi[i];

    for (int l = 0; l < LCLS; ++l) {
        float pt[8];
        #pragma unroll
        for (int t = 0; t < 8; ++t) {
            int n = l * 8 + t;
            float4 r4 = *(const float4*)(W + n * 2048 + c * 4);
            float rp[4] = {r4.x, r4.y, r4.z, r4.w};
            float acc = 0.0f;
            #pragma unroll
            for (int q = 0; q < 4; ++q) {
                float s = bpl[q];
                #pragma unroll
                for (int p = 0; p < 4; ++p) s += wpl[q * 4 + p] * rp[p];
                acc += sigmoidf_(s) * rp[q];
            }
            pt[t] = acc * 0.25f;
        }
        float acc2 = 0.0f;
        #pragma unroll
        for (int q = 0; q < 8; ++q) {
            float s = bil[q];
            #pragma unroll
            for (int t = 0; t < 8; ++t) s += wil[q * 8 + t] * pt[t];
            acc2 += sigmoidf_(s) * pt[q];
        }
        float v = acc2 * 0.125f;
        g_sem[l * CDIM + c] = v;
        out_semmat[l * CDIM + c] = v;
    }
}

// ---------------------------------------------------------------------------
// Kernel B: per 64-row tile — stage-3 attend (sem), then fused
// softmax(X@Wt) -> shrink -> L1 -> @W   (part-level attend)
// ---------------------------------------------------------------------------
__global__ __launch_bounds__(THREADS, 1)
void fused_attend_kernel(const float* __restrict__ X,
                         const float* __restrict__ W,
                         float* __restrict__ out_sem,
                         float* __restrict__ out_att,
                         float* __restrict__ out_part) {
    extern __shared__ float sm[];
    float* ATTs = sm + OFF_ATT;
    float* SEMs = sm + OFF_SEM;
    float* WSs  = sm + OFF_WS;
    float* XSs  = sm + OFF_XS;

    const int tid = threadIdx.x;
    const int tc = tid & 31;
    const int tr = tid >> 5;
    const int rowbase = blockIdx.x * BM;

    // load sem_att into smem
    for (int t = tid; t < LCLS * CDIM / 4; t += THREADS)
        *(float4*)&SEMs[t * 4] = *(const float4*)&g_sem[t * 4];
    __syncthreads();

    // ------------------- stage 3: attend over sem (L=10) -------------------
    #pragma unroll
    for (int i2 = 0; i2 < 2; ++i2) {
        float s3[4][10];
        #pragma unroll
        for (int k = 0; k < 4; ++k)
            #pragma unroll
            for (int l = 0; l < 10; ++l) s3[k][l] = 0.0f;

        #pragma unroll 4
        for (int u = 0; u < 16; ++u) {
            int cc = u * 32 + tc;
            float xv[4];
            #pragma unroll
            for (int k = 0; k < 4; ++k)
                xv[k] = X[(rowbase + tr * 8 + i2 * 4 + k) * CDIM + cc];
            #pragma unroll
            for (int l = 0; l < 10; ++l) {
                float sv = SEMs[l * CDIM + cc];
                #pragma unroll
                for (int k = 0; k < 4; ++k) s3[k][l] += xv[k] * sv;
            }
        }
        #pragma unroll
        for (int k = 0; k < 4; ++k) {
            #pragma unroll
            for (int l = 0; l < 10; ++l) s3[k][l] = wr_sum(s3[k][l]);
            float mx = s3[k][0];
            #pragma unroll
            for (int l = 1; l < 10; ++l) mx = fmaxf(mx, s3[k][l]);
            float se = 0.0f;
            #pragma unroll
            for (int l = 0; l < 10; ++l) { s3[k][l] = __expf(s3[k][l] - mx); se += s3[k][l]; }
            float inv = 1.0f / se;
            float l1 = 0.0f;
            #pragma unroll
            for (int l = 0; l < 10; ++l) {
                float a = s3[k][l] * inv;
                float t = a - SHRINK_L;
                float v = fmaxf(t, 0.0f) * a / (fabsf(t) + EPS_F);
                s3[k][l] = v; l1 += v;
            }
            float sc = 1.0f / fmaxf(l1, EPS_F);
            #pragma unroll
            for (int l = 0; l < 10; ++l) s3[k][l] *= sc;
            int rg = rowbase + tr * 8 + i2 * 4 + k;
            if (tc == 0) {
                #pragma unroll
                for (int l = 0; l < 10; ++l) out_att[rg * 10 + l] = s3[k][l];
            }
        }
        // readout with sem
        #pragma unroll 4
        for (int u = 0; u < 16; ++u) {
            int cc = u * 32 + tc;
            float acc[4] = {0.0f, 0.0f, 0.0f, 0.0f};
            #pragma unroll
            for (int l = 0; l < 10; ++l) {
                float sv = SEMs[l * CDIM + cc];
                #pragma unroll
                for (int k = 0; k < 4; ++k) acc[k] += s3[k][l] * sv;
            }
            #pragma unroll
            for (int k = 0; k < 4; ++k)
                out_sem[(rowbase + tr * 8 + i2 * 4 + k) * CDIM + cc] = acc[k];
        }
    }

    // ------------------- GEMM1: S[64,320] = X_tile @ W^T -------------------
    ull acc[8][5];
    #pragma unroll
    for (int i = 0; i < 8; ++i)
        #pragma unroll
        for (int j = 0; j < 5; ++j) acc[i][j] = 0ULL;

    for (int k0 = 0; k0 < CDIM; k0 += 32) {
        __syncthreads();
        // W tile, k-major in smem: WSs[kk][m], stride 322
        #pragma unroll
        for (int it = 0; it < 10; ++it) {
            int q = tid + it * THREADS;       // q < 2560
            int m = q >> 3, kq = q & 7;
            float4 w4 = *(const float4*)&W[m * CDIM + k0 + kq * 4];
            float* d = &WSs[(kq * 4) * WS_STRIDE + m];
            d[0] = w4.x; d[WS_STRIDE] = w4.y; d[2 * WS_STRIDE] = w4.z; d[3 * WS_STRIDE] = w4.w;
        }
        // X tile: XSs[r][kk], stride 36
        #pragma unroll
        for (int it = 0; it < 2; ++it) {
            int q = tid + it * THREADS;       // q < 512
            int r = q >> 3, kq = q & 7;
            float4 x4 = *(const float4*)&X[(rowbase + r) * CDIM + k0 + kq * 4];
            *(float4*)&XSs[r * XS_STRIDE + kq * 4] = x4;
        }
        __syncthreads();

        #pragma unroll 4
        for (int kk = 0; kk < 32; ++kk) {
            ull ap[8];
            #pragma unroll
            for (int i = 0; i < 8; ++i) {
                float a = XSs[(tr * 8 + i) * XS_STRIDE + kk];
                ap[i] = pack2(a, a);
            }
            #pragma unroll
            for (int j = 0; j < 5; ++j) {
                ull b = *(const ull*)&WSs[kk * WS_STRIDE + j * 64 + tc * 2];
                #pragma unroll
                for (int i = 0; i < 8; ++i) ffma2(acc[i][j], ap[i], b);
            }
        }
    }

    // --------- epilogue: softmax over 320, shrink, L1, to ATTs smem ---------
    #pragma unroll
    for (int i = 0; i < 8; ++i) {
        float sv[10];
        #pragma unroll
        for (int j = 0; j < 5; ++j) unpack2(acc[i][j], sv[2 * j], sv[2 * j + 1]);
        float mx = sv[0];
        #pragma unroll
        for (int x = 1; x < 10; ++x) mx = fmaxf(mx, sv[x]);
        mx = wr_max(mx);
        float se = 0.0f;
        #pragma unroll
        for (int x = 0; x < 10; ++x) { sv[x] = __expf(sv[x] - mx); se += sv[x]; }
        se = wr_sum(se);
        float inv = 1.0f / se;
        float l1 = 0.0f;
        #pragma unroll
        for (int x = 0; x < 10; ++x) {
            float a = sv[x] * inv;
            float t = a - SHRINK_L;
            float v = fmaxf(t, 0.0f) * a / (fabsf(t) + EPS_F);
            sv[x] = v; l1 += v;
        }
        l1 = wr_sum(l1);
        float sc = 1.0f / fmaxf(l1, EPS_F);
        #pragma unroll
        for (int j = 0; j < 5; ++j) {
            float2 p; p.x = sv[2 * j] * sc; p.y = sv[2 * j + 1] * sc;
            *(float2*)&ATTs[(tr * 8 + i) * MDIM + j * 64 + tc * 2] = p;
        }
    }

    // ------------- readout GEMM: O[64,512] = ATTs[64,320] @ W --------------
    #pragma unroll
    for (int ct = 0; ct < 2; ++ct) {
        ull acc2[8][4];
        #pragma unroll
        for (int i = 0; i < 8; ++i)
            #pragma unroll
            for (int j = 0; j < 4; ++j) acc2[i][j] = 0ULL;

        for (int k0 = 0; k0 < MDIM; k0 += 32) {
            __syncthreads();
            // W rows k0..k0+31, col half ct: WSs[kk][cc], stride 260
            #pragma unroll
            for (int it = 0; it < 8; ++it) {
                int q = tid + it * THREADS;   // q < 2048
                int kk = q >> 6, cc = (q & 63) << 2;
                *(float4*)&WSs[kk * WS2_STRIDE + cc] =
                    *(const float4*)&W[(k0 + kk) * CDIM + ct * 256 + cc];
            }
            __syncthreads();

            #pragma unroll 4
            for (int kk = 0; kk < 32; ++kk) {
                ull ap[8];
                #pragma unroll
                for (int i = 0; i < 8; ++i) {
                    float a = ATTs[(tr * 8 + i) * MDIM + k0 + kk];
                    ap[i] = pack2(a, a);
                }
                #pragma unroll
                for (int j = 0; j < 4; ++j) {
                    ull b = *(const ull*)&WSs[kk * WS2_STRIDE + j * 64 + tc * 2];
                    #pragma unroll
                    for (int i = 0; i < 8; ++i) ffma2(acc2[i][j], ap[i], b);
                }
            }
        }
        #pragma unroll
        for (int i = 0; i < 8; ++i) {
            int rg = rowbase + tr * 8 + i;
            #pragma unroll
            for (int j = 0; j < 4; ++j) {
                float lo, hi; unpack2(acc2[i][j], lo, hi);
                float2 p; p.x = lo; p.y = hi;
                *(float2*)&out_part[rg * CDIM + ct * 256 + j * 64 + tc * 2] = p;
            }
        }
    }
}

extern "C" void kernel_launch(void* const* d_in, const int* in_sizes, int n_in,
                              void* d_out, int out_size) {
    const float* X  = (const float*)d_in[0];
    const float* W  = (const float*)d_in[1];
    const float* wp = (const float*)d_in[2];
    const float* bp = (const float*)d_in[3];
    const float* wi = (const float*)d_in[4];
    const float* bi = (const float*)d_in[5];

    int N = in_sizes[0] / CDIM;   // 131072

    float* out       = (float*)d_out;
    float* out_sem   = out;                                   // [N, 512]
    float* out_att   = out + (size_t)N * CDIM;                // [N, 10]
    float* out_semm  = out_att + (size_t)N * LCLS;            // [10, 512]
    float* out_part  = out_semm + (size_t)LCLS * CDIM;        // [N, 512]

    sem_build_kernel<<<1, 512>>>(W, wp, bp, wi, bi, out_semm);

    int smem_bytes = SMEM_FLOATS * 4;
    cudaFuncSetAttribute(fused_attend_kernel,
                         cudaFuncAttributeMaxDynamicSharedMemorySize, smem_bytes);
    fused_attend_kernel<<<N / BM, THREADS, smem_bytes>>>(X, W, out_sem, out_att, out_part);
}